// round 9
// baseline (speedup 1.0000x reference)
#include <cuda_runtime.h>
#include <cstdint>

// Blur_by_Kernel: per-batch 21x21 depthwise correlation, reflect pad 10.
// B=16, C=3, H=W=768, K=21.
// R5: pre-duplicated kernel pairs in smem (no dup2 ALU), 512-thread CTA
// (4 warps/SMSP), template-specialized branchless steady loop.

#define SW 148                      // smem patch row stride (floats), mult of 4
#define PATCH_ROWS 148
#define PATCH (SW * PATCH_ROWS)     // 21904 floats
#define SMEM_KD_BYTES 3536          // 441 ull pairs (3528) padded to 16B
#define SMEM_BYTES (SMEM_KD_BYTES + PATCH * 4)   // 91152

typedef unsigned long long ull;

__device__ __forceinline__ ull dup2(float v) {
    ull r;
    asm("mov.b64 %0, {%1, %1};" : "=l"(r) : "f"(v));
    return r;
}

// returns pair (hi(a), lo(b)) -- the 1-element-shifted pair
__device__ __forceinline__ ull mid2(ull a, ull b) {
    ull r;
    asm("{\n\t"
        ".reg .b32 al, ah, bl, bh;\n\t"
        "mov.b64 {al, ah}, %1;\n\t"
        "mov.b64 {bl, bh}, %2;\n\t"
        "mov.b64 %0, {ah, bl};\n\t"
        "}"
        : "=l"(r) : "l"(a), "l"(b));
    return r;
}

__device__ __forceinline__ void ffma2(ull& d, ull a, ull b) {
    asm("fma.rn.f32x2 %0, %1, %2, %0;" : "+l"(d) : "l"(a), "l"(b));
}

// Process one input row rr against kernel rows for output rows iy in [IYLO, IYHI].
// Per-thread x tile: 8 outputs = 4 f32x2 pairs. Needs 28 input floats.
template<int IYLO, int IYHI>
__device__ __forceinline__ void process_row(const float* __restrict__ row,
                                            const ull* __restrict__ skd,
                                            ull (&acc)[4][4], int rr)
{
    // 28 floats -> 14 aligned pairs
    ull rp[14];
#pragma unroll
    for (int c = 0; c < 7; ++c) {
        ulonglong2 v = *reinterpret_cast<const ulonglong2*>(row + c * 4);
        rp[2 * c]     = v.x;
        rp[2 * c + 1] = v.y;
    }
    // shifted pairs: sp[h] = (r[2h+1], r[2h+2])
    ull sp[13];
#pragma unroll
    for (int h = 0; h < 13; ++h)
        sp[h] = mid2(rp[h], rp[h + 1]);

#pragma unroll
    for (int iy = IYLO; iy <= IYHI; ++iy) {
        const ull* kr = skd + (rr - iy) * 21;   // kernel row, pre-duplicated pairs
#pragma unroll
        for (int j = 0; j < 21; ++j) {
            const ull kb = kr[j];               // LDS.64 broadcast (k, k)
            const int h = j >> 1;
            if ((j & 1) == 0) {
                ffma2(acc[iy][0], rp[h + 0], kb);
                ffma2(acc[iy][1], rp[h + 1], kb);
                ffma2(acc[iy][2], rp[h + 2], kb);
                ffma2(acc[iy][3], rp[h + 3], kb);
            } else {
                ffma2(acc[iy][0], sp[h + 0], kb);
                ffma2(acc[iy][1], sp[h + 1], kb);
                ffma2(acc[iy][2], sp[h + 2], kb);
                ffma2(acc[iy][3], sp[h + 3], kb);
            }
        }
    }
}

__global__ void __launch_bounds__(512, 1)
blur21_kernel(const float* __restrict__ gin_all,
              const float* __restrict__ gker,
              float* __restrict__ gout_all)
{
    extern __shared__ char smem_raw[];
    ull*   s_kd = reinterpret_cast<ull*>(smem_raw);             // [441] (k,k) pairs
    float* s_in = reinterpret_cast<float*>(smem_raw + SMEM_KD_BYTES); // [148*148]

    const int tid = threadIdx.x;
    const int bc  = blockIdx.z;           // b*3 + c, 0..47
    const int b   = bc / 3;

    const float* gin = gin_all + (size_t)bc * (768 * 768);
    const float* gk  = gker + b * 441;

    const int x0 = blockIdx.x * 128 - 10;
    const int y0 = blockIdx.y * 128 - 10;

    // ---- fill smem patch with reflect indexing ----
    for (int idx = tid; idx < PATCH; idx += 512) {
        int py = idx / SW;
        int px = idx - py * SW;
        int gy = y0 + py;
        gy = (gy < 0) ? -gy : gy;
        gy = (gy > 767) ? (1534 - gy) : gy;
        int gx = x0 + px;
        gx = (gx < 0) ? -gx : gx;
        gx = (gx > 767) ? (1534 - gx) : gx;
        s_in[idx] = gin[gy * 768 + gx];
    }
    // ---- fill kernel as pre-duplicated (k,k) pairs ----
    for (int idx = tid; idx < 441; idx += 512)
        s_kd[idx] = dup2(gk[idx]);
    __syncthreads();

    // thread -> 8 x-outputs (4 f32x2 pairs) x 4 y-outputs
    const int lx = tid & 15;    // 0..15 -> x block of 8
    const int ly = tid >> 4;    // 0..31 -> y block of 4
    const int xb = lx * 8;

    ull acc[4][4];
#pragma unroll
    for (int iy = 0; iy < 4; ++iy)
#pragma unroll
        for (int p = 0; p < 4; ++p)
            acc[iy][p] = 0ULL;   // bit pattern of (0.0f, 0.0f)

    const float* base = s_in + (ly * 4) * SW + xb;

    // prologue rows 0..2 (partial iy coverage)
    process_row<0, 0>(base + 0 * SW, s_kd, acc, 0);
    process_row<0, 1>(base + 1 * SW, s_kd, acc, 1);
    process_row<0, 2>(base + 2 * SW, s_kd, acc, 2);
    // steady rows 3..20: all 4 output rows active, branchless
    for (int rr = 3; rr < 21; ++rr)
        process_row<0, 3>(base + rr * SW, s_kd, acc, rr);
    // epilogue rows 21..23
    process_row<1, 3>(base + 21 * SW, s_kd, acc, 21);
    process_row<2, 3>(base + 22 * SW, s_kd, acc, 22);
    process_row<3, 3>(base + 23 * SW, s_kd, acc, 23);

    // ---- store 8x4 outputs, 16B vector stores ----
    float* gout = gout_all + (size_t)bc * (768 * 768)
                + (size_t)(blockIdx.y * 128 + ly * 4) * 768
                + blockIdx.x * 128 + xb;
#pragma unroll
    for (int iy = 0; iy < 4; ++iy) {
        ulonglong2* o = reinterpret_cast<ulonglong2*>(gout + iy * 768);
        o[0] = make_ulonglong2(acc[iy][0], acc[iy][1]);
        o[1] = make_ulonglong2(acc[iy][2], acc[iy][3]);
    }
}

extern "C" void kernel_launch(void* const* d_in, const int* in_sizes, int n_in,
                              void* d_out, int out_size)
{
    const float* inp = (const float*)d_in[0];   // (16,3,768,768) f32
    const float* ker = (const float*)d_in[1];   // (16,21,21) f32
    float* out = (float*)d_out;                 // (16,3,768,768) f32

    cudaFuncSetAttribute(blur21_kernel,
                         cudaFuncAttributeMaxDynamicSharedMemorySize,
                         SMEM_BYTES);

    dim3 grid(6, 6, 48);   // 768/128 x-tiles, 768/128 y-tiles, 16*3 images
    blur21_kernel<<<grid, 512, SMEM_BYTES>>>(inp, ker, out);
}

// round 11
// speedup vs baseline: 1.0681x; 1.0681x over previous
#include <cuda_runtime.h>
#include <cstdint>

// Blur_by_Kernel: per-batch 21x21 depthwise correlation, reflect pad 10.
// B=16, C=3, H=W=768, K=21.
// R9: R4 tile shape (16x4 per thread, 8:1 FFMA2:kernel-LDS) + pre-duplicated
// kernel pairs in smem + templated edge rows + forced 2 CTAs/SM.

#define SW 148                      // smem patch row stride (floats), mult of 4
#define PATCH_ROWS 148
#define PATCH (SW * PATCH_ROWS)     // 21904 floats
#define SMEM_KD_BYTES 3536          // 441 ull pairs (3528) padded to 16B
#define SMEM_BYTES (SMEM_KD_BYTES + PATCH * 4)   // 91152 -> 2 CTAs = 182KB <= 228KB

typedef unsigned long long ull;

__device__ __forceinline__ ull dup2(float v) {
    ull r;
    asm("mov.b64 %0, {%1, %1};" : "=l"(r) : "f"(v));
    return r;
}

// returns pair (hi(a), lo(b)) -- the 1-element-shifted pair
__device__ __forceinline__ ull mid2(ull a, ull b) {
    ull r;
    asm("{\n\t"
        ".reg .b32 al, ah, bl, bh;\n\t"
        "mov.b64 {al, ah}, %1;\n\t"
        "mov.b64 {bl, bh}, %2;\n\t"
        "mov.b64 %0, {ah, bl};\n\t"
        "}"
        : "=l"(r) : "l"(a), "l"(b));
    return r;
}

__device__ __forceinline__ void ffma2(ull& d, ull a, ull b) {
    asm("fma.rn.f32x2 %0, %1, %2, %0;" : "+l"(d) : "l"(a), "l"(b));
}

// One input row rr against output rows iy in [IYLO, IYHI].
// Per-thread x tile: 16 outputs = 8 f32x2 pairs. Needs 36 input floats.
template<int IYLO, int IYHI>
__device__ __forceinline__ void process_row(const float* __restrict__ row,
                                            const ull* __restrict__ skd,
                                            ull (&acc)[4][8], int rr)
{
    // 36 floats -> 18 aligned pairs
    ull rp[18];
#pragma unroll
    for (int c = 0; c < 9; ++c) {
        ulonglong2 v = *reinterpret_cast<const ulonglong2*>(row + c * 4);
        rp[2 * c]     = v.x;
        rp[2 * c + 1] = v.y;
    }
    // shifted pairs: sp[h] = (r[2h+1], r[2h+2])
    ull sp[17];
#pragma unroll
    for (int h = 0; h < 17; ++h)
        sp[h] = mid2(rp[h], rp[h + 1]);

#pragma unroll
    for (int iy = IYLO; iy <= IYHI; ++iy) {
        const ull* kr = skd + (rr - iy) * 21;   // pre-duplicated (k,k) pairs
#pragma unroll
        for (int j = 0; j < 21; ++j) {
            const ull kb = kr[j];               // LDS.64 broadcast
            const int h = j >> 1;
            if ((j & 1) == 0) {
                ffma2(acc[iy][0], rp[h + 0], kb);
                ffma2(acc[iy][1], rp[h + 1], kb);
                ffma2(acc[iy][2], rp[h + 2], kb);
                ffma2(acc[iy][3], rp[h + 3], kb);
                ffma2(acc[iy][4], rp[h + 4], kb);
                ffma2(acc[iy][5], rp[h + 5], kb);
                ffma2(acc[iy][6], rp[h + 6], kb);
                ffma2(acc[iy][7], rp[h + 7], kb);
            } else {
                ffma2(acc[iy][0], sp[h + 0], kb);
                ffma2(acc[iy][1], sp[h + 1], kb);
                ffma2(acc[iy][2], sp[h + 2], kb);
                ffma2(acc[iy][3], sp[h + 3], kb);
                ffma2(acc[iy][4], sp[h + 4], kb);
                ffma2(acc[iy][5], sp[h + 5], kb);
                ffma2(acc[iy][6], sp[h + 6], kb);
                ffma2(acc[iy][7], sp[h + 7], kb);
            }
        }
    }
}

__global__ void __launch_bounds__(256, 2)
blur21_kernel(const float* __restrict__ gin_all,
              const float* __restrict__ gker,
              float* __restrict__ gout_all)
{
    extern __shared__ char smem_raw[];
    ull*   s_kd = reinterpret_cast<ull*>(smem_raw);                   // [441] (k,k)
    float* s_in = reinterpret_cast<float*>(smem_raw + SMEM_KD_BYTES); // [148*148]

    const int tid = threadIdx.x;
    const int bc  = blockIdx.z;           // b*3 + c, 0..47
    const int b   = bc / 3;

    const float* gin = gin_all + (size_t)bc * (768 * 768);
    const float* gk  = gker + b * 441;

    const int x0 = blockIdx.x * 128 - 10;
    const int y0 = blockIdx.y * 128 - 10;

    // ---- fill smem patch, division-free: warp per row slice ----
    {
        const int warp = tid >> 5;
        const int lane = tid & 31;
        for (int py = warp; py < PATCH_ROWS; py += 8) {
            int gy = y0 + py;
            gy = (gy < 0) ? -gy : gy;
            gy = (gy > 767) ? (1534 - gy) : gy;
            const float* grow = gin + gy * 768;
            float* srow = s_in + py * SW;
#pragma unroll
            for (int px = lane; px < SW; px += 32) {
                int gx = x0 + px;
                gx = (gx < 0) ? -gx : gx;
                gx = (gx > 767) ? (1534 - gx) : gx;
                srow[px] = grow[gx];
            }
        }
    }
    // ---- fill kernel as pre-duplicated (k,k) pairs ----
    for (int idx = tid; idx < 441; idx += 256)
        s_kd[idx] = dup2(gk[idx]);
    __syncthreads();

    // thread -> 16 x-outputs (8 pairs) x 4 y-outputs
    const int lx = tid & 7;     // 0..7  -> x block of 16
    const int ly = tid >> 3;    // 0..31 -> y block of 4
    const int xb = lx * 16;

    ull acc[4][8];
#pragma unroll
    for (int iy = 0; iy < 4; ++iy)
#pragma unroll
        for (int p = 0; p < 8; ++p)
            acc[iy][p] = 0ULL;

    const float* base = s_in + (ly * 4) * SW + xb;

    // prologue rows 0..2 (partial iy coverage)
    process_row<0, 0>(base + 0 * SW, s_kd, acc, 0);
    process_row<0, 1>(base + 1 * SW, s_kd, acc, 1);
    process_row<0, 2>(base + 2 * SW, s_kd, acc, 2);
    // steady rows 3..20: all 4 output rows active, branchless body, real loop
#pragma unroll 1
    for (int rr = 3; rr < 21; ++rr)
        process_row<0, 3>(base + rr * SW, s_kd, acc, rr);
    // epilogue rows 21..23
    process_row<1, 3>(base + 21 * SW, s_kd, acc, 21);
    process_row<2, 3>(base + 22 * SW, s_kd, acc, 22);
    process_row<3, 3>(base + 23 * SW, s_kd, acc, 23);

    // ---- store 16x4 outputs, 16B vector stores ----
    float* gout = gout_all + (size_t)bc * (768 * 768)
                + (size_t)(blockIdx.y * 128 + ly * 4) * 768
                + blockIdx.x * 128 + xb;
#pragma unroll
    for (int iy = 0; iy < 4; ++iy) {
        ulonglong2* o = reinterpret_cast<ulonglong2*>(gout + iy * 768);
        o[0] = make_ulonglong2(acc[iy][0], acc[iy][1]);
        o[1] = make_ulonglong2(acc[iy][2], acc[iy][3]);
        o[2] = make_ulonglong2(acc[iy][4], acc[iy][5]);
        o[3] = make_ulonglong2(acc[iy][6], acc[iy][7]);
    }
}

extern "C" void kernel_launch(void* const* d_in, const int* in_sizes, int n_in,
                              void* d_out, int out_size)
{
    const float* inp = (const float*)d_in[0];   // (16,3,768,768) f32
    const float* ker = (const float*)d_in[1];   // (16,21,21) f32
    float* out = (float*)d_out;                 // (16,3,768,768) f32

    cudaFuncSetAttribute(blur21_kernel,
                         cudaFuncAttributeMaxDynamicSharedMemorySize,
                         SMEM_BYTES);

    dim3 grid(6, 6, 48);   // 768/128 x-tiles, 768/128 y-tiles, 16*3 images
    blur21_kernel<<<grid, 256, SMEM_BYTES>>>(inp, ker, out);
}